// round 13
// baseline (speedup 1.0000x reference)
#include <cuda_runtime.h>
#include <cstdint>

// ---------------------------------------------------------------------------
// Flow net R13: 3-buffer cp.async pipeline (2 copies in flight, wait_group 1),
// upsample-algebra decoder convs, fused BN stats, merged zero pass.
// ---------------------------------------------------------------------------

#define EPSV   1e-5f
#define SLOPEV 0.01f

// scratch layout (floats)
#define OFF_F0R    0u          // raw enc0 out      8*64*8192  = 4194304
#define OFF_T0     4194304u    // bn(f0)
#define OFF_F1R    8388608u    // raw enc1 out      8*128*4096 = 4194304
#define OFF_T1     12582912u   // bn(f1)
#define OFF_F2R    16777216u   // raw enc2 out      8*256*2048 = 4194304
#define OFF_FEAT   20971520u   // fusion out (half-res) 8*11*2048 = 180224
#define OFF_D1R    21151744u   // raw dec1 out      4194304
#define OFF_TD1    25346048u   // bn(d1) half-res   4194304
#define OFF_D0R    29540352u   // raw dec0 out      8388608
#define OFF_FL     37928960u   // flow raw          262144
#define OFF_SUM    38191104u   // 706
#define OFF_SQS    38191810u   // 706
#define SCRATCH_TOTAL 38192516u

__device__ float g_scratch[SCRATCH_TOTAL];

typedef unsigned long long u64t;

#define FMA2(acc, x, w) \
    asm("fma.rn.f32x2 %0, %1, %2, %0;" : "+l"(acc) : "l"(x), "l"(w))
#define PACK2(out, lo, hi) \
    asm("mov.b64 %0, {%1, %2};" : "=l"(out) : "f"(lo), "f"(hi))
#define UNPACK2(lo, hi, in) \
    asm("mov.b64 {%0, %1}, %2;" : "=f"(lo), "=f"(hi) : "l"(in))

__device__ __forceinline__ float bnl(float r, float sc, float sh) {
    float a = sc * r + sh;
    return a >= 0.f ? a : SLOPEV * a;
}

__device__ __forceinline__ void cp16(unsigned dst, const float* src, int bytes) {
    asm volatile("cp.async.ca.shared.global [%0], [%1], 16, %2;"
                 :: "r"(dst), "l"(src), "r"(bytes));
}

// ---------------------------------------------------------------------------
__global__ void zero2_kernel(float* a, int na, float* b, int nb) {
    int i = blockIdx.x * 256 + threadIdx.x;
    if (i < na) a[i] = 0.f;
    if (i < nb) b[i] = 0.f;
}

// ---------------------------------------------------------------------------
// Encoder K=3 conv. 256 threads -> 1024 pos x 8 outch. 3-buffer cp.async
// pipeline with up to 2 copies in flight.
// ---------------------------------------------------------------------------
template<int STRIDE, int CT>
__global__ __launch_bounds__(256, 3)
void conv3_cp(const float* __restrict__ src1, int C1,
              int Lin, int Lout, int Cin, int CinPad,
              const float* __restrict__ w, const float* __restrict__ bias,
              float* __restrict__ y,
              float* __restrict__ gsum, float* __restrict__ gsqs)
{
    constexpr int TP = 1024;
    constexpr int TW = TP * STRIDE + 8;
    constexpr int NV = TW / 4;
    constexpr int XN = 4 * STRIDE + 5;
    constexpr int NQ = 3 * STRIDE + 3;

    extern __shared__ float sh[];
    __shared__ float redS[8], redQ[8];

    const int tid = threadIdx.x;
    const int P0  = blockIdx.x * TP;
    const int co0 = blockIdx.y * 8;
    const int b   = blockIdx.z;
    const int hs  = P0 * STRIDE - 4;
    const int wsN = CinPad * 24;
    float* ws = sh;
    float* xs = sh + wsN;

    if (tid < 8) { redS[tid] = 0.f; redQ[tid] = 0.f; }

    for (int idx = tid; idx < wsN; idx += 256) {
        int ci = idx / 24;
        int r  = idx - ci * 24;
        int k  = r >> 3, u = r & 7;
        ws[idx] = (ci < Cin) ? w[((size_t)(co0 + u) * Cin + ci) * 3 + k] : 0.f;
    }

    u64t acc[4][4];
    #pragma unroll
    for (int j = 0; j < 4; j++)
        #pragma unroll
        for (int u = 0; u < 4; u++) acc[j][u] = 0ull;

    const int ntile = CinPad / CT;

    auto stage = [&](int t, int buf) {
        float* xb = xs + buf * (CT * TW);
        int ci0 = t * CT;
        #pragma unroll
        for (int ci = 0; ci < CT; ci++) {
            int cg = ci0 + ci;
            bool cv = (cg < Cin);
            const float* row = src1 + (size_t)(b * C1 + (cv ? cg : 0)) * Lin;
            unsigned sb = (unsigned)__cvta_generic_to_shared(xb + ci * TW);
            for (int v = tid; v < NV; v += 256) {
                int p   = hs + v * 4;
                int okb = (cv && p >= 0 && p < Lin) ? 16 : 0;
                int pc  = min(max(p, 0), Lin - 4);
                cp16(sb + v * 16, row + pc, okb);
            }
        }
    };

    stage(0, 0);
    asm volatile("cp.async.commit_group;");
    if (ntile > 1) {
        stage(1, 1);
        asm volatile("cp.async.commit_group;");
    }

    for (int t = 0; t < ntile; t++) {
        if (t + 1 < ntile) asm volatile("cp.async.wait_group 1;");
        else               asm volatile("cp.async.wait_group 0;");
        __syncthreads();
        if (t + 2 < ntile) {
            stage(t + 2, (t + 2) % 3);
            asm volatile("cp.async.commit_group;");
        }
        const float* xbc = xs + (t % 3) * (CT * TW);
        #pragma unroll
        for (int ci = 0; ci < CT; ci++) {
            int gci = t * CT + ci;
            const float* xr = xbc + ci * TW + tid * 4 * STRIDE;
            float xv[XN];
            {
                float4 a0 = *(const float4*)xr;
                float4 a1 = *(const float4*)(xr + 4);
                xv[0] = a0.x; xv[1] = a0.y; xv[2] = a0.z; xv[3] = a0.w;
                xv[4] = a1.x; xv[5] = a1.y; xv[6] = a1.z; xv[7] = a1.w;
                if (STRIDE == 1) {
                    xv[8] = xr[8];
                } else {
                    float4 a2 = *(const float4*)(xr + 8);
                    xv[8] = a2.x; xv[9] = a2.y; xv[10] = a2.z; xv[11] = a2.w;
                    xv[12] = 0.f;
                }
            }
            u64t xq[NQ];
            #pragma unroll
            for (int i = 0; i < NQ; i++) PACK2(xq[i], xv[i + 3], xv[i + 3]);

            const char* wbase = (const char*)(ws + gci * 24);
            #pragma unroll
            for (int k = 0; k < 3; k++) {
                ulonglong2 wa = *(const ulonglong2*)(wbase + k * 32);
                ulonglong2 wb = *(const ulonglong2*)(wbase + k * 32 + 16);
                #pragma unroll
                for (int j = 0; j < 4; j++) {
                    u64t xqv = xq[j * STRIDE + k];
                    FMA2(acc[j][0], xqv, wa.x);
                    FMA2(acc[j][1], xqv, wa.y);
                    FMA2(acc[j][2], xqv, wb.x);
                    FMA2(acc[j][3], xqv, wb.y);
                }
            }
        }
    }

    // epilogue
    const int lid = tid & 31;
    #pragma unroll
    for (int u = 0; u < 4; u++) {
        float o0[4], o1[4];
        #pragma unroll
        for (int j = 0; j < 4; j++) UNPACK2(o0[j], o1[j], acc[j][u]);
        int c0 = co0 + 2 * u;
        float b0 = bias[c0], b1 = bias[c0 + 1];
        float s0 = 0.f, q0 = 0.f, s1 = 0.f, q1 = 0.f;
        #pragma unroll
        for (int j = 0; j < 4; j++) {
            o0[j] += b0; o1[j] += b1;
            s0 += o0[j]; q0 += o0[j] * o0[j];
            s1 += o1[j]; q1 += o1[j] * o1[j];
        }
        *(float4*)&y[((size_t)(b * (gridDim.y * 8) + c0)) * Lout + P0 + tid * 4] =
            make_float4(o0[0], o0[1], o0[2], o0[3]);
        *(float4*)&y[((size_t)(b * (gridDim.y * 8) + c0 + 1)) * Lout + P0 + tid * 4] =
            make_float4(o1[0], o1[1], o1[2], o1[3]);
        unsigned full = 0xffffffffu;
        #pragma unroll
        for (int o = 16; o > 0; o >>= 1) {
            s0 += __shfl_down_sync(full, s0, o);
            q0 += __shfl_down_sync(full, q0, o);
            s1 += __shfl_down_sync(full, s1, o);
            q1 += __shfl_down_sync(full, q1, o);
        }
        if (lid == 0) {
            atomicAdd(&redS[2 * u], s0);     atomicAdd(&redQ[2 * u], q0);
            atomicAdd(&redS[2 * u + 1], s1); atomicAdd(&redQ[2 * u + 1], q1);
        }
    }
    __syncthreads();
    if (tid < 8) {
        atomicAdd(&gsum[co0 + tid], redS[tid]);
        atomicAdd(&gsqs[co0 + tid], redQ[tid]);
    }
}

// ---------------------------------------------------------------------------
// Decoder conv: src1 full-res (3-tap) + src2 HALF-res (2-tap upsample
// algebra). 3-buffer cp.async pipeline.
// ---------------------------------------------------------------------------
template<int CT>
__global__ __launch_bounds__(256, 3)
void conv3_mix(const float* __restrict__ src1, int C1,
               const float* __restrict__ src2, int C2, int C2Pad,
               int Lin, int Cout,
               const float* __restrict__ w, const float* __restrict__ bias,
               float* __restrict__ y,
               float* __restrict__ gsum, float* __restrict__ gsqs)
{
    constexpr int TP  = 1024;
    constexpr int TW1 = TP + 8;        // 1032
    constexpr int TW2 = TP / 2 + 8;    // 520
    constexpr int NV1 = TW1 / 4;
    constexpr int NV2 = TW2 / 4;

    extern __shared__ float sh[];
    __shared__ float redS[8], redQ[8];

    const int tid = threadIdx.x;
    const int P0  = blockIdx.x * TP;
    const int co0 = blockIdx.y * 8;
    const int b   = blockIdx.z;
    const int Lin2 = Lin >> 1;
    const int hs1 = P0 - 4;
    const int hs2 = P0 / 2 - 4;
    const int Cin = C1 + C2;

    const int ws3N = C1 * 24;
    const int ws2N = C2Pad * 32;
    float* ws3 = sh;
    float* ws2 = sh + ws3N;
    float* xs  = sh + ws3N + ws2N;

    if (tid < 8) { redS[tid] = 0.f; redQ[tid] = 0.f; }

    for (int idx = tid; idx < ws3N; idx += 256) {
        int ci = idx / 24;
        int r  = idx - ci * 24;
        int k  = r >> 3, u = r & 7;
        ws3[idx] = w[((size_t)(co0 + u) * Cin + ci) * 3 + k];
    }
    for (int idx = tid; idx < C2Pad * 8; idx += 256) {
        int ci2 = idx / 8;
        int u   = idx & 7;
        float w0 = 0.f, w1 = 0.f, w2 = 0.f;
        if (ci2 < C2) {
            const float* wp = &w[((size_t)(co0 + u) * Cin + C1 + ci2) * 3];
            w0 = wp[0]; w1 = wp[1]; w2 = wp[2];
        }
        float* base = ws2 + ci2 * 32;
        base[0 * 8 + u] = w0;
        base[1 * 8 + u] = w1 + w2;
        base[2 * 8 + u] = w0 + w1;
        base[3 * 8 + u] = w2;
    }

    u64t acc[4][4];
    #pragma unroll
    for (int j = 0; j < 4; j++)
        #pragma unroll
        for (int u = 0; u < 4; u++) acc[j][u] = 0ull;

    const int nt1 = C1 / CT;
    const int nt2 = C2Pad / CT;
    const int ntile = nt1 + nt2;

    auto stage = [&](int t, int buf) {
        if (t < nt1) {
            float* xb = xs + buf * (CT * TW1);
            int ci0 = t * CT;
            #pragma unroll
            for (int ci = 0; ci < CT; ci++) {
                const float* row = src1 + (size_t)(b * C1 + ci0 + ci) * Lin;
                unsigned sb = (unsigned)__cvta_generic_to_shared(xb + ci * TW1);
                for (int v = tid; v < NV1; v += 256) {
                    int p   = hs1 + v * 4;
                    int okb = (p >= 0 && p < Lin) ? 16 : 0;
                    int pc  = min(max(p, 0), Lin - 4);
                    cp16(sb + v * 16, row + pc, okb);
                }
            }
        } else {
            float* xb = xs + buf * (CT * TW1);
            int ci0 = (t - nt1) * CT;
            #pragma unroll
            for (int ci = 0; ci < CT; ci++) {
                int cg = ci0 + ci;
                bool cv = (cg < C2);
                const float* row = src2 + (size_t)(b * C2 + (cv ? cg : 0)) * Lin2;
                unsigned sb = (unsigned)__cvta_generic_to_shared(xb + ci * TW2);
                for (int v = tid; v < NV2; v += 256) {
                    int p   = hs2 + v * 4;
                    int okb = (cv && p >= 0 && p < Lin2) ? 16 : 0;
                    int pc  = min(max(p, 0), Lin2 - 4);
                    cp16(sb + v * 16, row + pc, okb);
                }
            }
        }
    };

    stage(0, 0);
    asm volatile("cp.async.commit_group;");
    if (ntile > 1) {
        stage(1, 1);
        asm volatile("cp.async.commit_group;");
    }

    for (int t = 0; t < ntile; t++) {
        if (t + 1 < ntile) asm volatile("cp.async.wait_group 1;");
        else               asm volatile("cp.async.wait_group 0;");
        __syncthreads();
        if (t + 2 < ntile) {
            stage(t + 2, (t + 2) % 3);
            asm volatile("cp.async.commit_group;");
        }
        const float* xbc = xs + (t % 3) * (CT * TW1);
        if (t < nt1) {
            #pragma unroll
            for (int ci = 0; ci < CT; ci++) {
                int gci = t * CT + ci;
                const float* xr = xbc + ci * TW1 + tid * 4;
                float4 a0 = *(const float4*)xr;
                float4 a1 = *(const float4*)(xr + 4);
                float x8 = xr[8];
                float xv[9] = {a0.x, a0.y, a0.z, a0.w, a1.x, a1.y, a1.z, a1.w, x8};
                u64t xq[6];
                #pragma unroll
                for (int i = 0; i < 6; i++) PACK2(xq[i], xv[i + 3], xv[i + 3]);
                const char* wbase = (const char*)(ws3 + gci * 24);
                #pragma unroll
                for (int k = 0; k < 3; k++) {
                    ulonglong2 wa = *(const ulonglong2*)(wbase + k * 32);
                    ulonglong2 wb = *(const ulonglong2*)(wbase + k * 32 + 16);
                    #pragma unroll
                    for (int j = 0; j < 4; j++) {
                        u64t xqv = xq[j + k];
                        FMA2(acc[j][0], xqv, wa.x);
                        FMA2(acc[j][1], xqv, wa.y);
                        FMA2(acc[j][2], xqv, wb.x);
                        FMA2(acc[j][3], xqv, wb.y);
                    }
                }
            }
        } else {
            #pragma unroll
            for (int ci = 0; ci < CT; ci++) {
                int gci2 = (t - nt1) * CT + ci;
                const float* hr = xbc + ci * TW2 + tid * 2;
                float2 p0 = *(const float2*)(hr + 2);
                float2 p1 = *(const float2*)(hr + 4);
                float2 p2 = *(const float2*)(hr + 6);
                float hm = p0.y, h0 = p1.x, h1 = p1.y, h2 = p2.x;
                u64t qm, q0, q1, q2;
                PACK2(qm, hm, hm); PACK2(q0, h0, h0);
                PACK2(q1, h1, h1); PACK2(q2, h2, h2);
                const char* wbase = (const char*)(ws2 + gci2 * 32);
                ulonglong2 wA0 = *(const ulonglong2*)(wbase);
                ulonglong2 wA1 = *(const ulonglong2*)(wbase + 16);
                ulonglong2 wB0 = *(const ulonglong2*)(wbase + 32);
                ulonglong2 wB1 = *(const ulonglong2*)(wbase + 48);
                ulonglong2 wC0 = *(const ulonglong2*)(wbase + 64);
                ulonglong2 wC1 = *(const ulonglong2*)(wbase + 80);
                ulonglong2 wD0 = *(const ulonglong2*)(wbase + 96);
                ulonglong2 wD1 = *(const ulonglong2*)(wbase + 112);
                FMA2(acc[0][0], qm, wA0.x); FMA2(acc[0][1], qm, wA0.y);
                FMA2(acc[0][2], qm, wA1.x); FMA2(acc[0][3], qm, wA1.y);
                FMA2(acc[0][0], q0, wB0.x); FMA2(acc[0][1], q0, wB0.y);
                FMA2(acc[0][2], q0, wB1.x); FMA2(acc[0][3], q0, wB1.y);
                FMA2(acc[1][0], q0, wC0.x); FMA2(acc[1][1], q0, wC0.y);
                FMA2(acc[1][2], q0, wC1.x); FMA2(acc[1][3], q0, wC1.y);
                FMA2(acc[1][0], q1, wD0.x); FMA2(acc[1][1], q1, wD0.y);
                FMA2(acc[1][2], q1, wD1.x); FMA2(acc[1][3], q1, wD1.y);
                FMA2(acc[2][0], q0, wA0.x); FMA2(acc[2][1], q0, wA0.y);
                FMA2(acc[2][2], q0, wA1.x); FMA2(acc[2][3], q0, wA1.y);
                FMA2(acc[2][0], q1, wB0.x); FMA2(acc[2][1], q1, wB0.y);
                FMA2(acc[2][2], q1, wB1.x); FMA2(acc[2][3], q1, wB1.y);
                FMA2(acc[3][0], q1, wC0.x); FMA2(acc[3][1], q1, wC0.y);
                FMA2(acc[3][2], q1, wC1.x); FMA2(acc[3][3], q1, wC1.y);
                FMA2(acc[3][0], q2, wD0.x); FMA2(acc[3][1], q2, wD0.y);
                FMA2(acc[3][2], q2, wD1.x); FMA2(acc[3][3], q2, wD1.y);
            }
        }
    }

    // epilogue
    const int lid = tid & 31;
    #pragma unroll
    for (int u = 0; u < 4; u++) {
        float o0[4], o1[4];
        #pragma unroll
        for (int j = 0; j < 4; j++) UNPACK2(o0[j], o1[j], acc[j][u]);
        int c0 = co0 + 2 * u;
        float b0 = bias[c0], b1 = bias[c0 + 1];
        float s0 = 0.f, q0 = 0.f, s1 = 0.f, q1 = 0.f;
        #pragma unroll
        for (int j = 0; j < 4; j++) {
            o0[j] += b0; o1[j] += b1;
            s0 += o0[j]; q0 += o0[j] * o0[j];
            s1 += o1[j]; q1 += o1[j] * o1[j];
        }
        *(float4*)&y[((size_t)(b * Cout + c0)) * Lin + P0 + tid * 4] =
            make_float4(o0[0], o0[1], o0[2], o0[3]);
        *(float4*)&y[((size_t)(b * Cout + c0 + 1)) * Lin + P0 + tid * 4] =
            make_float4(o1[0], o1[1], o1[2], o1[3]);
        unsigned full = 0xffffffffu;
        #pragma unroll
        for (int o = 16; o > 0; o >>= 1) {
            s0 += __shfl_down_sync(full, s0, o);
            q0 += __shfl_down_sync(full, q0, o);
            s1 += __shfl_down_sync(full, s1, o);
            q1 += __shfl_down_sync(full, q1, o);
        }
        if (lid == 0) {
            atomicAdd(&redS[2 * u], s0);     atomicAdd(&redQ[2 * u], q0);
            atomicAdd(&redS[2 * u + 1], s1); atomicAdd(&redQ[2 * u + 1], q1);
        }
    }
    __syncthreads();
    if (tid < 8) {
        atomicAdd(&gsum[co0 + tid], redS[tid]);
        atomicAdd(&gsqs[co0 + tid], redQ[tid]);
    }
}

// ---------------------------------------------------------------------------
__global__ __launch_bounds__(256)
void bn_out_kernel(const float* __restrict__ raw, float* __restrict__ out,
                   int C, int L,
                   const float* __restrict__ ssum, const float* __restrict__ sqs,
                   const float* __restrict__ g, const float* __restrict__ be,
                   float invn)
{
    size_t i4 = (size_t)blockIdx.x * 256 + threadIdx.x;
    int c = (int)((i4 * 4) / (size_t)L) % C;
    float m   = ssum[c] * invn;
    float var = sqs[c] * invn - m * m;
    float sc  = g[c] * rsqrtf(var + EPSV);
    float sh  = be[c] - sc * m;
    float4 v = ((const float4*)raw)[i4];
    float4 o;
    o.x = bnl(v.x, sc, sh); o.y = bnl(v.y, sc, sh);
    o.z = bnl(v.z, sc, sh); o.w = bnl(v.w, sc, sh);
    ((float4*)out)[i4] = o;
}

// ---------------------------------------------------------------------------
// Fusion: banded correlation, BN fused into staging, channel-split,
// half-res output via atomics.
// ---------------------------------------------------------------------------
__global__ __launch_bounds__(128)
void fusion_kernel(const float* __restrict__ f2r, float* __restrict__ feat,
                   const float* __restrict__ ssum, const float* __restrict__ sqs,
                   const float* __restrict__ gamma, const float* __restrict__ beta,
                   float invn)
{
    const int Nn = 2048, C = 256;
    const int b   = blockIdx.y;
    const int i0  = blockIdx.x * 128;
    const int cb  = blockIdx.z * 64;
    const int tid = threadIdx.x;
    const int i   = i0 + tid;
    __shared__ float tile[16][144];
    __shared__ float csc[64], csh[64];

    if (tid < 64) {
        int c = cb + tid;
        float m = ssum[c] * invn;
        float var = sqs[c] * invn - m * m;
        float sc = gamma[c] * rsqrtf(var + EPSV);
        csc[tid] = sc;
        csh[tid] = beta[c] - sc * m;
    }

    float acc[11];
    #pragma unroll
    for (int d = 0; d < 11; d++) acc[d] = 0.f;

    const bool interior = (i >= 5) && (i <= Nn - 6);

    for (int c0 = 0; c0 < 64; c0 += 16) {
        __syncthreads();
        for (int idx = tid; idx < 16 * 140; idx += 128) {
            int c = idx / 140, off = idx - c * 140;
            int p = i0 - 6 + off;
            p = min(max(p, 0), Nn - 1);
            float r = f2r[((size_t)(b * C + cb + c0 + c)) * Nn + p];
            tile[c][off] = bnl(r, csc[c0 + c], csh[c0 + c]);
        }
        __syncthreads();
        for (int c = 0; c < 16; c++) {
            float v[13];
            #pragma unroll
            for (int m = 0; m < 13; m++) v[m] = tile[c][tid + m];
            float A0 = v[5], A1 = v[6], A2 = v[7];
            if (interior) {
                #pragma unroll
                for (int dd = 0; dd < 11; dd++)
                    acc[dd] += A0 * v[dd] + A1 * v[dd + 1] + A2 * v[dd + 2];
            } else {
                for (int dd = 0; dd < 11; dd++) {
                    int j = i + dd - 5;
                    j = min(max(j, 0), Nn - 1);
                    int o0 = max(j - 1, 0) - i0 + 6;
                    int o1 = j - i0 + 6;
                    int o2 = min(j + 1, Nn - 1) - i0 + 6;
                    acc[dd] += A0 * tile[c][o0] + A1 * tile[c][o1] + A2 * tile[c][o2];
                }
            }
        }
    }
    #pragma unroll
    for (int dd = 0; dd < 11; dd++)
        atomicAdd(&feat[((size_t)(b * 11 + dd)) * 2048 + i], acc[dd]);
}

// ---------------------------------------------------------------------------
// Flow head with fused BN stats.
// ---------------------------------------------------------------------------
__global__ __launch_bounds__(256)
void flow_conv_kernel(const float* __restrict__ x1, const float* __restrict__ d0,
                      const float* __restrict__ w, const float* __restrict__ bias,
                      const float* __restrict__ ssum, const float* __restrict__ sqs,
                      const float* __restrict__ gamma, const float* __restrict__ beta,
                      float invn,
                      float* __restrict__ out,
                      float* __restrict__ osum, float* __restrict__ osqs)
{
    const int Nn = 16384;
    __shared__ float csc[128], csh[128];
    __shared__ float redS[2], redQ[2];
    int tid = threadIdx.x;
    if (tid < 128) {
        float m = ssum[tid] * invn;
        float var = sqs[tid] * invn - m * m;
        float sc = gamma[tid] * rsqrtf(var + EPSV);
        csc[tid] = sc;
        csh[tid] = beta[tid] - sc * m;
    }
    if (tid < 2) { redS[tid] = 0.f; redQ[tid] = 0.f; }
    __syncthreads();

    int b = blockIdx.y;
    int i = blockIdx.x * 256 + tid;
    float2 xv = ((const float2*)&x1[(size_t)b * Nn])[i];
    float a00 = w[0] * xv.x, a01 = w[0] * xv.y;
    float a10 = w[129] * xv.x, a11 = w[129] * xv.y;
    const float* dp = d0 + (size_t)b * 128 * 8192 + i;
    #pragma unroll 4
    for (int ci = 0; ci < 128; ci++) {
        float r = dp[(size_t)ci * 8192];
        float v = bnl(r, csc[ci], csh[ci]);
        a00 += w[1 + ci] * v;   a01 += w[1 + ci] * v;
        a10 += w[130 + ci] * v; a11 += w[130 + ci] * v;
    }
    float v00 = a00 + bias[0], v01 = a01 + bias[0];
    float v10 = a10 + bias[1], v11 = a11 + bias[1];
    ((float2*)&out[((size_t)(b * 2 + 0)) * Nn])[i] = make_float2(v00, v01);
    ((float2*)&out[((size_t)(b * 2 + 1)) * Nn])[i] = make_float2(v10, v11);

    float s0 = v00 + v01, q0 = v00 * v00 + v01 * v01;
    float s1 = v10 + v11, q1 = v10 * v10 + v11 * v11;
    unsigned full = 0xffffffffu;
    #pragma unroll
    for (int o = 16; o > 0; o >>= 1) {
        s0 += __shfl_down_sync(full, s0, o);
        q0 += __shfl_down_sync(full, q0, o);
        s1 += __shfl_down_sync(full, s1, o);
        q1 += __shfl_down_sync(full, q1, o);
    }
    if ((tid & 31) == 0) {
        atomicAdd(&redS[0], s0); atomicAdd(&redQ[0], q0);
        atomicAdd(&redS[1], s1); atomicAdd(&redQ[1], q1);
    }
    __syncthreads();
    if (tid < 2) {
        atomicAdd(&osum[tid], redS[tid]);
        atomicAdd(&osqs[tid], redQ[tid]);
    }
}

// ---------------------------------------------------------------------------
__global__ __launch_bounds__(256)
void flow_apply_kernel(const float* __restrict__ fl,
                       const float* __restrict__ ssum, const float* __restrict__ sqs,
                       const float* __restrict__ gamma, const float* __restrict__ beta,
                       float* __restrict__ out, float invn)
{
    const int Nn = 16384;
    int b = blockIdx.y;
    int p = blockIdx.x * 256 + threadIdx.x;
    float m0 = ssum[0] * invn, m1 = ssum[1] * invn;
    float v0 = sqs[0] * invn - m0 * m0;
    float v1 = sqs[1] * invn - m1 * m1;
    float sc0 = gamma[0] * rsqrtf(v0 + EPSV), sh0 = beta[0] - sc0 * m0;
    float sc1 = gamma[1] * rsqrtf(v1 + EPSV), sh1 = beta[1] - sc1 * m1;
    float a = fl[((size_t)(b * 2 + 0)) * Nn + p];
    float c = fl[((size_t)(b * 2 + 1)) * Nn + p];
    float2 r;
    r.x = bnl(a, sc0, sh0);
    r.y = bnl(c, sc1, sh1);
    ((float2*)out)[(size_t)b * Nn + p] = r;
}

// ---------------------------------------------------------------------------
extern "C" void kernel_launch(void* const* d_in, const int* in_sizes, int n_in,
                              void* d_out, int out_size)
{
    (void)in_sizes; (void)n_in; (void)out_size;
    const float* scan1 = (const float*)d_in[0];
    const float* e0w = (const float*)d_in[1];
    const float* e0b = (const float*)d_in[2];
    const float* e0g = (const float*)d_in[3];
    const float* e0e = (const float*)d_in[4];
    const float* e1w = (const float*)d_in[5];
    const float* e1b = (const float*)d_in[6];
    const float* e1g = (const float*)d_in[7];
    const float* e1e = (const float*)d_in[8];
    const float* e2w = (const float*)d_in[9];
    const float* e2b = (const float*)d_in[10];
    const float* e2g = (const float*)d_in[11];
    const float* e2e = (const float*)d_in[12];
    const float* d1w = (const float*)d_in[13];
    const float* d1b = (const float*)d_in[14];
    const float* d1g = (const float*)d_in[15];
    const float* d1e = (const float*)d_in[16];
    const float* d0w = (const float*)d_in[17];
    const float* d0b = (const float*)d_in[18];
    const float* d0g = (const float*)d_in[19];
    const float* d0e = (const float*)d_in[20];
    const float* fw  = (const float*)d_in[21];
    const float* fb  = (const float*)d_in[22];
    const float* fg  = (const float*)d_in[23];
    const float* fe  = (const float*)d_in[24];

    float* base = nullptr;
    cudaGetSymbolAddress((void**)&base, g_scratch);
    float* f0r  = base + OFF_F0R;
    float* t0   = base + OFF_T0;
    float* f1r  = base + OFF_F1R;
    float* t1   = base + OFF_T1;
    float* f2r  = base + OFF_F2R;
    float* feat = base + OFF_FEAT;
    float* d1r  = base + OFF_D1R;
    float* td1  = base + OFF_TD1;
    float* d0r  = base + OFF_D0R;
    float* fl   = base + OFF_FL;
    float* sum  = base + OFF_SUM;
    float* sqs  = base + OFF_SQS;

    const float i0n = 1.f / (8.f * 8192.f);
    const float i1n = 1.f / (8.f * 4096.f);
    const float i2n = 1.f / (8.f * 2048.f);

    // smem sizes (bytes): weights + 3 x-buffers
    const int SM_E0 = (1 * 24 + 3 * 1 * 2056) * 4;                 // 24768
    const int SM_E1 = (64 * 24 + 3 * 2 * 2056) * 4;                // 55488
    const int SM_E2 = (128 * 24 + 3 * 2 * 2056) * 4;               // 61632
    const int SM_D1 = (128 * 24 + 12 * 32 + 3 * 4 * 1032) * 4;     // 63360
    const int SM_D0 = (64 * 24 + 128 * 32 + 3 * 4 * 1032) * 4;     // 72064
    cudaFuncSetAttribute(conv3_cp<2, 1>, cudaFuncAttributeMaxDynamicSharedMemorySize, SM_E0);
    cudaFuncSetAttribute(conv3_cp<2, 2>, cudaFuncAttributeMaxDynamicSharedMemorySize, SM_E2);
    cudaFuncSetAttribute(conv3_mix<4>, cudaFuncAttributeMaxDynamicSharedMemorySize, SM_D0);

    zero2_kernel<<<704, 256>>>(sum, 1412, feat, 180224);

    // enc0
    conv3_cp<2, 1><<<dim3(8, 8, 8), 256, SM_E0>>>(
        scan1, 1, 16384, 8192, 1, 1, e0w, e0b, f0r, sum + 0, sqs + 0);
    bn_out_kernel<<<4096, 256>>>(f0r, t0, 64, 8192, sum + 0, sqs + 0, e0g, e0e, i0n);

    // enc1
    conv3_cp<2, 2><<<dim3(4, 16, 8), 256, SM_E1>>>(
        t0, 64, 8192, 4096, 64, 64, e1w, e1b, f1r, sum + 64, sqs + 64);
    bn_out_kernel<<<4096, 256>>>(f1r, t1, 128, 4096, sum + 64, sqs + 64, e1g, e1e, i1n);

    // enc2
    conv3_cp<2, 2><<<dim3(2, 32, 8), 256, SM_E2>>>(
        t1, 128, 4096, 2048, 128, 128, e2w, e2b, f2r, sum + 192, sqs + 192);

    // fusion -> feat (half-res)
    fusion_kernel<<<dim3(16, 8, 4), 128>>>(f2r, feat,
                                           sum + 192, sqs + 192, e2g, e2e, i2n);

    // dec1: src1 = t1 (128, full 4096), src2 = feat (11, half 2048)
    conv3_mix<4><<<dim3(4, 16, 8), 256, SM_D1>>>(
        t1, 128, feat, 11, 12, 4096, 128,
        d1w, d1b, d1r, sum + 448, sqs + 448);
    bn_out_kernel<<<4096, 256>>>(d1r, td1, 128, 4096, sum + 448, sqs + 448, d1g, d1e, i1n);

    // dec0: src1 = t0 (64, full 8192), src2 = td1 (128, half 4096)
    conv3_mix<4><<<dim3(8, 16, 8), 256, SM_D0>>>(
        t0, 64, td1, 128, 128, 8192, 128,
        d0w, d0b, d0r, sum + 576, sqs + 576);

    // flow head (stats fused)
    flow_conv_kernel<<<dim3(32, 8), 256>>>(scan1, d0r, fw, fb,
                                           sum + 576, sqs + 576, d0g, d0e, i0n,
                                           fl, sum + 704, sqs + 704);
    flow_apply_kernel<<<dim3(64, 8), 256>>>(fl, sum + 704, sqs + 704, fg, fe,
                                            (float*)d_out, 1.f / (8.f * 16384.f));
}

// round 14
// speedup vs baseline: 1.0716x; 1.0716x over previous
#include <cuda_runtime.h>
#include <cstdint>

// ---------------------------------------------------------------------------
// Flow net R14: R12 double-buffer base + interior fast-path staging (no
// predicates/clamps for in-bounds tiles), tight stride-2 window (2052),
// upsample-algebra decoders, fused BN stats, merged zero pass.
// ---------------------------------------------------------------------------

#define EPSV   1e-5f
#define SLOPEV 0.01f

// scratch layout (floats)
#define OFF_F0R    0u          // raw enc0 out      8*64*8192  = 4194304
#define OFF_T0     4194304u    // bn(f0)
#define OFF_F1R    8388608u    // raw enc1 out      8*128*4096 = 4194304
#define OFF_T1     12582912u   // bn(f1)
#define OFF_F2R    16777216u   // raw enc2 out      8*256*2048 = 4194304
#define OFF_FEAT   20971520u   // fusion out (half-res) 8*11*2048 = 180224
#define OFF_D1R    21151744u   // raw dec1 out      4194304
#define OFF_TD1    25346048u   // bn(d1) half-res   4194304
#define OFF_D0R    29540352u   // raw dec0 out      8388608
#define OFF_FL     37928960u   // flow raw          262144
#define OFF_SUM    38191104u   // 706
#define OFF_SQS    38191810u   // 706
#define SCRATCH_TOTAL 38192516u

__device__ float g_scratch[SCRATCH_TOTAL];

typedef unsigned long long u64t;

#define FMA2(acc, x, w) \
    asm("fma.rn.f32x2 %0, %1, %2, %0;" : "+l"(acc) : "l"(x), "l"(w))
#define PACK2(out, lo, hi) \
    asm("mov.b64 %0, {%1, %2};" : "=l"(out) : "f"(lo), "f"(hi))
#define UNPACK2(lo, hi, in) \
    asm("mov.b64 {%0, %1}, %2;" : "=f"(lo), "=f"(hi) : "l"(in))

__device__ __forceinline__ float bnl(float r, float sc, float sh) {
    float a = sc * r + sh;
    return a >= 0.f ? a : SLOPEV * a;
}

__device__ __forceinline__ void cp16(unsigned dst, const float* src, int bytes) {
    asm volatile("cp.async.ca.shared.global [%0], [%1], 16, %2;"
                 :: "r"(dst), "l"(src), "r"(bytes));
}
__device__ __forceinline__ void cp16u(unsigned dst, const float* src) {
    asm volatile("cp.async.ca.shared.global [%0], [%1], 16;"
                 :: "r"(dst), "l"(src));
}

// ---------------------------------------------------------------------------
__global__ void zero2_kernel(float* a, int na, float* b, int nb) {
    int i = blockIdx.x * 256 + threadIdx.x;
    if (i < na) a[i] = 0.f;
    if (i < nb) b[i] = 0.f;
}

// ---------------------------------------------------------------------------
// Encoder K=3 conv, double-buffered cp.async, interior fast-path staging.
// 256 threads -> 1024 pos x 8 outch. Cin == CinPad for all encoder calls.
// ---------------------------------------------------------------------------
template<int STRIDE, int CT>
__global__ __launch_bounds__(256, 3)
void conv3_cp(const float* __restrict__ src1, int C1,
              int Lin, int Lout, int Cin,
              const float* __restrict__ w, const float* __restrict__ bias,
              float* __restrict__ y,
              float* __restrict__ gsum, float* __restrict__ gsqs)
{
    constexpr int TP = 1024;
    constexpr int TW = (STRIDE == 2) ? (TP * 2 + 4) : (TP + 8);  // 2052 / 1032
    constexpr int NV = TW / 4;
    constexpr int XN = 4 * STRIDE + 5;
    constexpr int NQ = 3 * STRIDE + 3;

    extern __shared__ float sh[];
    __shared__ float redS[8], redQ[8];

    const int tid = threadIdx.x;
    const int P0  = blockIdx.x * TP;
    const int co0 = blockIdx.y * 8;
    const int b   = blockIdx.z;
    const int hs  = P0 * STRIDE - 4;
    const int wsN = Cin * 24;
    float* ws = sh;
    float* xs = sh + wsN;
    const bool interior = (hs >= 0) && (hs + TW <= Lin);

    if (tid < 8) { redS[tid] = 0.f; redQ[tid] = 0.f; }

    for (int idx = tid; idx < wsN; idx += 256) {
        int ci = idx / 24;
        int r  = idx - ci * 24;
        int k  = r >> 3, u = r & 7;
        ws[idx] = w[((size_t)(co0 + u) * Cin + ci) * 3 + k];
    }

    u64t acc[4][4];
    #pragma unroll
    for (int j = 0; j < 4; j++)
        #pragma unroll
        for (int u = 0; u < 4; u++) acc[j][u] = 0ull;

    const int ntile = Cin / CT;

    auto stage = [&](int t, int buf) {
        float* xb = xs + buf * (CT * TW);
        int ci0 = t * CT;
        if (interior) {
            #pragma unroll
            for (int ci = 0; ci < CT; ci++) {
                const float* row = src1 + (size_t)(b * C1 + ci0 + ci) * Lin + hs;
                unsigned sb = (unsigned)__cvta_generic_to_shared(xb + ci * TW);
                for (int v = tid; v < NV; v += 256)
                    cp16u(sb + v * 16, row + v * 4);
            }
        } else {
            #pragma unroll
            for (int ci = 0; ci < CT; ci++) {
                const float* row = src1 + (size_t)(b * C1 + ci0 + ci) * Lin;
                unsigned sb = (unsigned)__cvta_generic_to_shared(xb + ci * TW);
                for (int v = tid; v < NV; v += 256) {
                    int p   = hs + v * 4;
                    int okb = (p >= 0 && p < Lin) ? 16 : 0;
                    int pc  = min(max(p, 0), Lin - 4);
                    cp16(sb + v * 16, row + pc, okb);
                }
            }
        }
    };

    stage(0, 0);
    asm volatile("cp.async.commit_group;");

    for (int t = 0; t < ntile; t++) {
        asm volatile("cp.async.wait_group 0;");
        __syncthreads();
        if (t + 1 < ntile) {
            stage(t + 1, (t + 1) & 1);
            asm volatile("cp.async.commit_group;");
        }
        const float* xbc = xs + (t & 1) * (CT * TW);
        #pragma unroll
        for (int ci = 0; ci < CT; ci++) {
            int gci = t * CT + ci;
            const float* xr = xbc + ci * TW + tid * 4 * STRIDE;
            float xv[XN];
            {
                float4 a0 = *(const float4*)xr;
                float4 a1 = *(const float4*)(xr + 4);
                xv[0] = a0.x; xv[1] = a0.y; xv[2] = a0.z; xv[3] = a0.w;
                xv[4] = a1.x; xv[5] = a1.y; xv[6] = a1.z; xv[7] = a1.w;
                if (STRIDE == 1) {
                    xv[8] = xr[8];
                } else {
                    float4 a2 = *(const float4*)(xr + 8);
                    xv[8] = a2.x; xv[9] = a2.y; xv[10] = a2.z; xv[11] = a2.w;
                    xv[12] = 0.f;
                }
            }
            u64t xq[NQ];
            #pragma unroll
            for (int i = 0; i < NQ; i++) PACK2(xq[i], xv[i + 3], xv[i + 3]);

            const char* wbase = (const char*)(ws + gci * 24);
            #pragma unroll
            for (int k = 0; k < 3; k++) {
                ulonglong2 wa = *(const ulonglong2*)(wbase + k * 32);
                ulonglong2 wb = *(const ulonglong2*)(wbase + k * 32 + 16);
                #pragma unroll
                for (int j = 0; j < 4; j++) {
                    u64t xqv = xq[j * STRIDE + k];
                    FMA2(acc[j][0], xqv, wa.x);
                    FMA2(acc[j][1], xqv, wa.y);
                    FMA2(acc[j][2], xqv, wb.x);
                    FMA2(acc[j][3], xqv, wb.y);
                }
            }
        }
    }

    // epilogue
    const int lid = tid & 31;
    #pragma unroll
    for (int u = 0; u < 4; u++) {
        float o0[4], o1[4];
        #pragma unroll
        for (int j = 0; j < 4; j++) UNPACK2(o0[j], o1[j], acc[j][u]);
        int c0 = co0 + 2 * u;
        float b0 = bias[c0], b1 = bias[c0 + 1];
        float s0 = 0.f, q0 = 0.f, s1 = 0.f, q1 = 0.f;
        #pragma unroll
        for (int j = 0; j < 4; j++) {
            o0[j] += b0; o1[j] += b1;
            s0 += o0[j]; q0 += o0[j] * o0[j];
            s1 += o1[j]; q1 += o1[j] * o1[j];
        }
        *(float4*)&y[((size_t)(b * (gridDim.y * 8) + c0)) * Lout + P0 + tid * 4] =
            make_float4(o0[0], o0[1], o0[2], o0[3]);
        *(float4*)&y[((size_t)(b * (gridDim.y * 8) + c0 + 1)) * Lout + P0 + tid * 4] =
            make_float4(o1[0], o1[1], o1[2], o1[3]);
        unsigned full = 0xffffffffu;
        #pragma unroll
        for (int o = 16; o > 0; o >>= 1) {
            s0 += __shfl_down_sync(full, s0, o);
            q0 += __shfl_down_sync(full, q0, o);
            s1 += __shfl_down_sync(full, s1, o);
            q1 += __shfl_down_sync(full, q1, o);
        }
        if (lid == 0) {
            atomicAdd(&redS[2 * u], s0);     atomicAdd(&redQ[2 * u], q0);
            atomicAdd(&redS[2 * u + 1], s1); atomicAdd(&redQ[2 * u + 1], q1);
        }
    }
    __syncthreads();
    if (tid < 8) {
        atomicAdd(&gsum[co0 + tid], redS[tid]);
        atomicAdd(&gsqs[co0 + tid], redQ[tid]);
    }
}

// ---------------------------------------------------------------------------
// Decoder conv: src1 full-res (3-tap) + src2 HALF-res (2-tap upsample
// algebra). Double-buffered, interior fast-path staging.
// ---------------------------------------------------------------------------
template<int CT>
__global__ __launch_bounds__(256, 3)
void conv3_mix(const float* __restrict__ src1, int C1,
               const float* __restrict__ src2, int C2, int C2Pad,
               int Lin, int Cout,
               const float* __restrict__ w, const float* __restrict__ bias,
               float* __restrict__ y,
               float* __restrict__ gsum, float* __restrict__ gsqs)
{
    constexpr int TP  = 1024;
    constexpr int TW1 = TP + 8;        // 1032
    constexpr int TW2 = TP / 2 + 8;    // 520
    constexpr int NV1 = TW1 / 4;
    constexpr int NV2 = TW2 / 4;

    extern __shared__ float sh[];
    __shared__ float redS[8], redQ[8];

    const int tid = threadIdx.x;
    const int P0  = blockIdx.x * TP;
    const int co0 = blockIdx.y * 8;
    const int b   = blockIdx.z;
    const int Lin2 = Lin >> 1;
    const int hs1 = P0 - 4;
    const int hs2 = P0 / 2 - 4;
    const int Cin = C1 + C2;
    const bool int1 = (hs1 >= 0) && (hs1 + TW1 <= Lin);
    const bool int2 = (hs2 >= 0) && (hs2 + TW2 <= Lin2);

    const int ws3N = C1 * 24;
    const int ws2N = C2Pad * 32;
    float* ws3 = sh;
    float* ws2 = sh + ws3N;
    float* xs  = sh + ws3N + ws2N;

    if (tid < 8) { redS[tid] = 0.f; redQ[tid] = 0.f; }

    for (int idx = tid; idx < ws3N; idx += 256) {
        int ci = idx / 24;
        int r  = idx - ci * 24;
        int k  = r >> 3, u = r & 7;
        ws3[idx] = w[((size_t)(co0 + u) * Cin + ci) * 3 + k];
    }
    for (int idx = tid; idx < C2Pad * 8; idx += 256) {
        int ci2 = idx / 8;
        int u   = idx & 7;
        float w0 = 0.f, w1 = 0.f, w2 = 0.f;
        if (ci2 < C2) {
            const float* wp = &w[((size_t)(co0 + u) * Cin + C1 + ci2) * 3];
            w0 = wp[0]; w1 = wp[1]; w2 = wp[2];
        }
        float* base = ws2 + ci2 * 32;
        base[0 * 8 + u] = w0;
        base[1 * 8 + u] = w1 + w2;
        base[2 * 8 + u] = w0 + w1;
        base[3 * 8 + u] = w2;
    }

    u64t acc[4][4];
    #pragma unroll
    for (int j = 0; j < 4; j++)
        #pragma unroll
        for (int u = 0; u < 4; u++) acc[j][u] = 0ull;

    const int nt1 = C1 / CT;
    const int nt2 = C2Pad / CT;
    const int ntile = nt1 + nt2;

    auto stage = [&](int t, int buf) {
        float* xb = xs + buf * (CT * TW1);
        if (t < nt1) {
            int ci0 = t * CT;
            if (int1) {
                #pragma unroll
                for (int ci = 0; ci < CT; ci++) {
                    const float* row = src1 + (size_t)(b * C1 + ci0 + ci) * Lin + hs1;
                    unsigned sb = (unsigned)__cvta_generic_to_shared(xb + ci * TW1);
                    for (int v = tid; v < NV1; v += 256)
                        cp16u(sb + v * 16, row + v * 4);
                }
            } else {
                #pragma unroll
                for (int ci = 0; ci < CT; ci++) {
                    const float* row = src1 + (size_t)(b * C1 + ci0 + ci) * Lin;
                    unsigned sb = (unsigned)__cvta_generic_to_shared(xb + ci * TW1);
                    for (int v = tid; v < NV1; v += 256) {
                        int p   = hs1 + v * 4;
                        int okb = (p >= 0 && p < Lin) ? 16 : 0;
                        int pc  = min(max(p, 0), Lin - 4);
                        cp16(sb + v * 16, row + pc, okb);
                    }
                }
            }
        } else {
            int ci0 = (t - nt1) * CT;
            if (int2 && ci0 + CT <= C2) {
                #pragma unroll
                for (int ci = 0; ci < CT; ci++) {
                    const float* row = src2 + (size_t)(b * C2 + ci0 + ci) * Lin2 + hs2;
                    unsigned sb = (unsigned)__cvta_generic_to_shared(xb + ci * TW2);
                    for (int v = tid; v < NV2; v += 256)
                        cp16u(sb + v * 16, row + v * 4);
                }
            } else {
                #pragma unroll
                for (int ci = 0; ci < CT; ci++) {
                    int cg = ci0 + ci;
                    bool cv = (cg < C2);
                    const float* row = src2 + (size_t)(b * C2 + (cv ? cg : 0)) * Lin2;
                    unsigned sb = (unsigned)__cvta_generic_to_shared(xb + ci * TW2);
                    for (int v = tid; v < NV2; v += 256) {
                        int p   = hs2 + v * 4;
                        int okb = (cv && p >= 0 && p < Lin2) ? 16 : 0;
                        int pc  = min(max(p, 0), Lin2 - 4);
                        cp16(sb + v * 16, row + pc, okb);
                    }
                }
            }
        }
    };

    stage(0, 0);
    asm volatile("cp.async.commit_group;");

    for (int t = 0; t < ntile; t++) {
        asm volatile("cp.async.wait_group 0;");
        __syncthreads();
        if (t + 1 < ntile) {
            stage(t + 1, (t + 1) & 1);
            asm volatile("cp.async.commit_group;");
        }
        const float* xbc = xs + (t & 1) * (CT * TW1);
        if (t < nt1) {
            #pragma unroll
            for (int ci = 0; ci < CT; ci++) {
                int gci = t * CT + ci;
                const float* xr = xbc + ci * TW1 + tid * 4;
                float4 a0 = *(const float4*)xr;
                float4 a1 = *(const float4*)(xr + 4);
                float x8 = xr[8];
                float xv[9] = {a0.x, a0.y, a0.z, a0.w, a1.x, a1.y, a1.z, a1.w, x8};
                u64t xq[6];
                #pragma unroll
                for (int i = 0; i < 6; i++) PACK2(xq[i], xv[i + 3], xv[i + 3]);
                const char* wbase = (const char*)(ws3 + gci * 24);
                #pragma unroll
                for (int k = 0; k < 3; k++) {
                    ulonglong2 wa = *(const ulonglong2*)(wbase + k * 32);
                    ulonglong2 wb = *(const ulonglong2*)(wbase + k * 32 + 16);
                    #pragma unroll
                    for (int j = 0; j < 4; j++) {
                        u64t xqv = xq[j + k];
                        FMA2(acc[j][0], xqv, wa.x);
                        FMA2(acc[j][1], xqv, wa.y);
                        FMA2(acc[j][2], xqv, wb.x);
                        FMA2(acc[j][3], xqv, wb.y);
                    }
                }
            }
        } else {
            #pragma unroll
            for (int ci = 0; ci < CT; ci++) {
                int gci2 = (t - nt1) * CT + ci;
                const float* hr = xbc + ci * TW2 + tid * 2;
                float2 p0 = *(const float2*)(hr + 2);
                float2 p1 = *(const float2*)(hr + 4);
                float2 p2 = *(const float2*)(hr + 6);
                float hm = p0.y, h0 = p1.x, h1 = p1.y, h2 = p2.x;
                u64t qm, q0, q1, q2;
                PACK2(qm, hm, hm); PACK2(q0, h0, h0);
                PACK2(q1, h1, h1); PACK2(q2, h2, h2);
                const char* wbase = (const char*)(ws2 + gci2 * 32);
                ulonglong2 wA0 = *(const ulonglong2*)(wbase);
                ulonglong2 wA1 = *(const ulonglong2*)(wbase + 16);
                ulonglong2 wB0 = *(const ulonglong2*)(wbase + 32);
                ulonglong2 wB1 = *(const ulonglong2*)(wbase + 48);
                ulonglong2 wC0 = *(const ulonglong2*)(wbase + 64);
                ulonglong2 wC1 = *(const ulonglong2*)(wbase + 80);
                ulonglong2 wD0 = *(const ulonglong2*)(wbase + 96);
                ulonglong2 wD1 = *(const ulonglong2*)(wbase + 112);
                FMA2(acc[0][0], qm, wA0.x); FMA2(acc[0][1], qm, wA0.y);
                FMA2(acc[0][2], qm, wA1.x); FMA2(acc[0][3], qm, wA1.y);
                FMA2(acc[0][0], q0, wB0.x); FMA2(acc[0][1], q0, wB0.y);
                FMA2(acc[0][2], q0, wB1.x); FMA2(acc[0][3], q0, wB1.y);
                FMA2(acc[1][0], q0, wC0.x); FMA2(acc[1][1], q0, wC0.y);
                FMA2(acc[1][2], q0, wC1.x); FMA2(acc[1][3], q0, wC1.y);
                FMA2(acc[1][0], q1, wD0.x); FMA2(acc[1][1], q1, wD0.y);
                FMA2(acc[1][2], q1, wD1.x); FMA2(acc[1][3], q1, wD1.y);
                FMA2(acc[2][0], q0, wA0.x); FMA2(acc[2][1], q0, wA0.y);
                FMA2(acc[2][2], q0, wA1.x); FMA2(acc[2][3], q0, wA1.y);
                FMA2(acc[2][0], q1, wB0.x); FMA2(acc[2][1], q1, wB0.y);
                FMA2(acc[2][2], q1, wB1.x); FMA2(acc[2][3], q1, wB1.y);
                FMA2(acc[3][0], q1, wC0.x); FMA2(acc[3][1], q1, wC0.y);
                FMA2(acc[3][2], q1, wC1.x); FMA2(acc[3][3], q1, wC1.y);
                FMA2(acc[3][0], q2, wD0.x); FMA2(acc[3][1], q2, wD0.y);
                FMA2(acc[3][2], q2, wD1.x); FMA2(acc[3][3], q2, wD1.y);
            }
        }
    }

    // epilogue
    const int lid = tid & 31;
    #pragma unroll
    for (int u = 0; u < 4; u++) {
        float o0[4], o1[4];
        #pragma unroll
        for (int j = 0; j < 4; j++) UNPACK2(o0[j], o1[j], acc[j][u]);
        int c0 = co0 + 2 * u;
        float b0 = bias[c0], b1 = bias[c0 + 1];
        float s0 = 0.f, q0 = 0.f, s1 = 0.f, q1 = 0.f;
        #pragma unroll
        for (int j = 0; j < 4; j++) {
            o0[j] += b0; o1[j] += b1;
            s0 += o0[j]; q0 += o0[j] * o0[j];
            s1 += o1[j]; q1 += o1[j] * o1[j];
        }
        *(float4*)&y[((size_t)(b * Cout + c0)) * Lin + P0 + tid * 4] =
            make_float4(o0[0], o0[1], o0[2], o0[3]);
        *(float4*)&y[((size_t)(b * Cout + c0 + 1)) * Lin + P0 + tid * 4] =
            make_float4(o1[0], o1[1], o1[2], o1[3]);
        unsigned full = 0xffffffffu;
        #pragma unroll
        for (int o = 16; o > 0; o >>= 1) {
            s0 += __shfl_down_sync(full, s0, o);
            q0 += __shfl_down_sync(full, q0, o);
            s1 += __shfl_down_sync(full, s1, o);
            q1 += __shfl_down_sync(full, q1, o);
        }
        if (lid == 0) {
            atomicAdd(&redS[2 * u], s0);     atomicAdd(&redQ[2 * u], q0);
            atomicAdd(&redS[2 * u + 1], s1); atomicAdd(&redQ[2 * u + 1], q1);
        }
    }
    __syncthreads();
    if (tid < 8) {
        atomicAdd(&gsum[co0 + tid], redS[tid]);
        atomicAdd(&gsqs[co0 + tid], redQ[tid]);
    }
}

// ---------------------------------------------------------------------------
__global__ __launch_bounds__(256)
void bn_out_kernel(const float* __restrict__ raw, float* __restrict__ out,
                   int C, int L,
                   const float* __restrict__ ssum, const float* __restrict__ sqs,
                   const float* __restrict__ g, const float* __restrict__ be,
                   float invn)
{
    size_t i4 = (size_t)blockIdx.x * 256 + threadIdx.x;
    int c = (int)((i4 * 4) / (size_t)L) % C;
    float m   = ssum[c] * invn;
    float var = sqs[c] * invn - m * m;
    float sc  = g[c] * rsqrtf(var + EPSV);
    float sh  = be[c] - sc * m;
    float4 v = ((const float4*)raw)[i4];
    float4 o;
    o.x = bnl(v.x, sc, sh); o.y = bnl(v.y, sc, sh);
    o.z = bnl(v.z, sc, sh); o.w = bnl(v.w, sc, sh);
    ((float4*)out)[i4] = o;
}

// ---------------------------------------------------------------------------
// Fusion: banded correlation, BN fused into staging, channel-split,
// half-res output via atomics.
// ---------------------------------------------------------------------------
__global__ __launch_bounds__(128)
void fusion_kernel(const float* __restrict__ f2r, float* __restrict__ feat,
                   const float* __restrict__ ssum, const float* __restrict__ sqs,
                   const float* __restrict__ gamma, const float* __restrict__ beta,
                   float invn)
{
    const int Nn = 2048, C = 256;
    const int b   = blockIdx.y;
    const int i0  = blockIdx.x * 128;
    const int cb  = blockIdx.z * 64;
    const int tid = threadIdx.x;
    const int i   = i0 + tid;
    __shared__ float tile[16][144];
    __shared__ float csc[64], csh[64];

    if (tid < 64) {
        int c = cb + tid;
        float m = ssum[c] * invn;
        float var = sqs[c] * invn - m * m;
        float sc = gamma[c] * rsqrtf(var + EPSV);
        csc[tid] = sc;
        csh[tid] = beta[c] - sc * m;
    }

    float acc[11];
    #pragma unroll
    for (int d = 0; d < 11; d++) acc[d] = 0.f;

    const bool interior = (i >= 5) && (i <= Nn - 6);

    for (int c0 = 0; c0 < 64; c0 += 16) {
        __syncthreads();
        for (int idx = tid; idx < 16 * 140; idx += 128) {
            int c = idx / 140, off = idx - c * 140;
            int p = i0 - 6 + off;
            p = min(max(p, 0), Nn - 1);
            float r = f2r[((size_t)(b * C + cb + c0 + c)) * Nn + p];
            tile[c][off] = bnl(r, csc[c0 + c], csh[c0 + c]);
        }
        __syncthreads();
        for (int c = 0; c < 16; c++) {
            float v[13];
            #pragma unroll
            for (int m = 0; m < 13; m++) v[m] = tile[c][tid + m];
            float A0 = v[5], A1 = v[6], A2 = v[7];
            if (interior) {
                #pragma unroll
                for (int dd = 0; dd < 11; dd++)
                    acc[dd] += A0 * v[dd] + A1 * v[dd + 1] + A2 * v[dd + 2];
            } else {
                for (int dd = 0; dd < 11; dd++) {
                    int j = i + dd - 5;
                    j = min(max(j, 0), Nn - 1);
                    int o0 = max(j - 1, 0) - i0 + 6;
                    int o1 = j - i0 + 6;
                    int o2 = min(j + 1, Nn - 1) - i0 + 6;
                    acc[dd] += A0 * tile[c][o0] + A1 * tile[c][o1] + A2 * tile[c][o2];
                }
            }
        }
    }
    #pragma unroll
    for (int dd = 0; dd < 11; dd++)
        atomicAdd(&feat[((size_t)(b * 11 + dd)) * 2048 + i], acc[dd]);
}

// ---------------------------------------------------------------------------
// Flow head with fused BN stats.
// ---------------------------------------------------------------------------
__global__ __launch_bounds__(256)
void flow_conv_kernel(const float* __restrict__ x1, const float* __restrict__ d0,
                      const float* __restrict__ w, const float* __restrict__ bias,
                      const float* __restrict__ ssum, const float* __restrict__ sqs,
                      const float* __restrict__ gamma, const float* __restrict__ beta,
                      float invn,
                      float* __restrict__ out,
                      float* __restrict__ osum, float* __restrict__ osqs)
{
    const int Nn = 16384;
    __shared__ float csc[128], csh[128];
    __shared__ float redS[2], redQ[2];
    int tid = threadIdx.x;
    if (tid < 128) {
        float m = ssum[tid] * invn;
        float var = sqs[tid] * invn - m * m;
        float sc = gamma[tid] * rsqrtf(var + EPSV);
        csc[tid] = sc;
        csh[tid] = beta[tid] - sc * m;
    }
    if (tid < 2) { redS[tid] = 0.f; redQ[tid] = 0.f; }
    __syncthreads();

    int b = blockIdx.y;
    int i = blockIdx.x * 256 + tid;
    float2 xv = ((const float2*)&x1[(size_t)b * Nn])[i];
    float a00 = w[0] * xv.x, a01 = w[0] * xv.y;
    float a10 = w[129] * xv.x, a11 = w[129] * xv.y;
    const float* dp = d0 + (size_t)b * 128 * 8192 + i;
    #pragma unroll 4
    for (int ci = 0; ci < 128; ci++) {
        float r = dp[(size_t)ci * 8192];
        float v = bnl(r, csc[ci], csh[ci]);
        a00 += w[1 + ci] * v;   a01 += w[1 + ci] * v;
        a10 += w[130 + ci] * v; a11 += w[130 + ci] * v;
    }
    float v00 = a00 + bias[0], v01 = a01 + bias[0];
    float v10 = a10 + bias[1], v11 = a11 + bias[1];
    ((float2*)&out[((size_t)(b * 2 + 0)) * Nn])[i] = make_float2(v00, v01);
    ((float2*)&out[((size_t)(b * 2 + 1)) * Nn])[i] = make_float2(v10, v11);

    float s0 = v00 + v01, q0 = v00 * v00 + v01 * v01;
    float s1 = v10 + v11, q1 = v10 * v10 + v11 * v11;
    unsigned full = 0xffffffffu;
    #pragma unroll
    for (int o = 16; o > 0; o >>= 1) {
        s0 += __shfl_down_sync(full, s0, o);
        q0 += __shfl_down_sync(full, q0, o);
        s1 += __shfl_down_sync(full, s1, o);
        q1 += __shfl_down_sync(full, q1, o);
    }
    if ((tid & 31) == 0) {
        atomicAdd(&redS[0], s0); atomicAdd(&redQ[0], q0);
        atomicAdd(&redS[1], s1); atomicAdd(&redQ[1], q1);
    }
    __syncthreads();
    if (tid < 2) {
        atomicAdd(&osum[tid], redS[tid]);
        atomicAdd(&osqs[tid], redQ[tid]);
    }
}

// ---------------------------------------------------------------------------
__global__ __launch_bounds__(256)
void flow_apply_kernel(const float* __restrict__ fl,
                       const float* __restrict__ ssum, const float* __restrict__ sqs,
                       const float* __restrict__ gamma, const float* __restrict__ beta,
                       float* __restrict__ out, float invn)
{
    const int Nn = 16384;
    int b = blockIdx.y;
    int p = blockIdx.x * 256 + threadIdx.x;
    float m0 = ssum[0] * invn, m1 = ssum[1] * invn;
    float v0 = sqs[0] * invn - m0 * m0;
    float v1 = sqs[1] * invn - m1 * m1;
    float sc0 = gamma[0] * rsqrtf(v0 + EPSV), sh0 = beta[0] - sc0 * m0;
    float sc1 = gamma[1] * rsqrtf(v1 + EPSV), sh1 = beta[1] - sc1 * m1;
    float a = fl[((size_t)(b * 2 + 0)) * Nn + p];
    float c = fl[((size_t)(b * 2 + 1)) * Nn + p];
    float2 r;
    r.x = bnl(a, sc0, sh0);
    r.y = bnl(c, sc1, sh1);
    ((float2*)out)[(size_t)b * Nn + p] = r;
}

// ---------------------------------------------------------------------------
extern "C" void kernel_launch(void* const* d_in, const int* in_sizes, int n_in,
                              void* d_out, int out_size)
{
    (void)in_sizes; (void)n_in; (void)out_size;
    const float* scan1 = (const float*)d_in[0];
    const float* e0w = (const float*)d_in[1];
    const float* e0b = (const float*)d_in[2];
    const float* e0g = (const float*)d_in[3];
    const float* e0e = (const float*)d_in[4];
    const float* e1w = (const float*)d_in[5];
    const float* e1b = (const float*)d_in[6];
    const float* e1g = (const float*)d_in[7];
    const float* e1e = (const float*)d_in[8];
    const float* e2w = (const float*)d_in[9];
    const float* e2b = (const float*)d_in[10];
    const float* e2g = (const float*)d_in[11];
    const float* e2e = (const float*)d_in[12];
    const float* d1w = (const float*)d_in[13];
    const float* d1b = (const float*)d_in[14];
    const float* d1g = (const float*)d_in[15];
    const float* d1e = (const float*)d_in[16];
    const float* d0w = (const float*)d_in[17];
    const float* d0b = (const float*)d_in[18];
    const float* d0g = (const float*)d_in[19];
    const float* d0e = (const float*)d_in[20];
    const float* fw  = (const float*)d_in[21];
    const float* fb  = (const float*)d_in[22];
    const float* fg  = (const float*)d_in[23];
    const float* fe  = (const float*)d_in[24];

    float* base = nullptr;
    cudaGetSymbolAddress((void**)&base, g_scratch);
    float* f0r  = base + OFF_F0R;
    float* t0   = base + OFF_T0;
    float* f1r  = base + OFF_F1R;
    float* t1   = base + OFF_T1;
    float* f2r  = base + OFF_F2R;
    float* feat = base + OFF_FEAT;
    float* d1r  = base + OFF_D1R;
    float* td1  = base + OFF_TD1;
    float* d0r  = base + OFF_D0R;
    float* fl   = base + OFF_FL;
    float* sum  = base + OFF_SUM;
    float* sqs  = base + OFF_SQS;

    const float i0n = 1.f / (8.f * 8192.f);
    const float i1n = 1.f / (8.f * 4096.f);
    const float i2n = 1.f / (8.f * 2048.f);

    // smem sizes (bytes): weights + 2 x-buffers
    const int SM_E0 = (1 * 24 + 2 * 1 * 2052) * 4;                 // 16512
    const int SM_E1 = (64 * 24 + 2 * 2 * 2052) * 4;                // 38976
    const int SM_E2 = (128 * 24 + 2 * 2 * 2052) * 4;               // 45120
    const int SM_D1 = (128 * 24 + 12 * 32 + 2 * 4 * 1032) * 4;     // 46848
    const int SM_D0 = (64 * 24 + 128 * 32 + 2 * 4 * 1032) * 4;     // 55552
    cudaFuncSetAttribute(conv3_cp<2, 1>, cudaFuncAttributeMaxDynamicSharedMemorySize, SM_E0);
    cudaFuncSetAttribute(conv3_cp<2, 2>, cudaFuncAttributeMaxDynamicSharedMemorySize, SM_E2);
    cudaFuncSetAttribute(conv3_mix<4>, cudaFuncAttributeMaxDynamicSharedMemorySize, SM_D0);

    zero2_kernel<<<704, 256>>>(sum, 1412, feat, 180224);

    // enc0
    conv3_cp<2, 1><<<dim3(8, 8, 8), 256, SM_E0>>>(
        scan1, 1, 16384, 8192, 1, e0w, e0b, f0r, sum + 0, sqs + 0);
    bn_out_kernel<<<4096, 256>>>(f0r, t0, 64, 8192, sum + 0, sqs + 0, e0g, e0e, i0n);

    // enc1
    conv3_cp<2, 2><<<dim3(4, 16, 8), 256, SM_E1>>>(
        t0, 64, 8192, 4096, 64, e1w, e1b, f1r, sum + 64, sqs + 64);
    bn_out_kernel<<<4096, 256>>>(f1r, t1, 128, 4096, sum + 64, sqs + 64, e1g, e1e, i1n);

    // enc2
    conv3_cp<2, 2><<<dim3(2, 32, 8), 256, SM_E2>>>(
        t1, 128, 4096, 2048, 128, e2w, e2b, f2r, sum + 192, sqs + 192);

    // fusion -> feat (half-res)
    fusion_kernel<<<dim3(16, 8, 4), 128>>>(f2r, feat,
                                           sum + 192, sqs + 192, e2g, e2e, i2n);

    // dec1: src1 = t1 (128, full 4096), src2 = feat (11, half 2048)
    conv3_mix<4><<<dim3(4, 16, 8), 256, SM_D1>>>(
        t1, 128, feat, 11, 12, 4096, 128,
        d1w, d1b, d1r, sum + 448, sqs + 448);
    bn_out_kernel<<<4096, 256>>>(d1r, td1, 128, 4096, sum + 448, sqs + 448, d1g, d1e, i1n);

    // dec0: src1 = t0 (64, full 8192), src2 = td1 (128, half 4096)
    conv3_mix<4><<<dim3(8, 16, 8), 256, SM_D0>>>(
        t0, 64, td1, 128, 128, 8192, 128,
        d0w, d0b, d0r, sum + 576, sqs + 576);

    // flow head (stats fused)
    flow_conv_kernel<<<dim3(32, 8), 256>>>(scan1, d0r, fw, fb,
                                           sum + 576, sqs + 576, d0g, d0e, i0n,
                                           fl, sum + 704, sqs + 704);
    flow_apply_kernel<<<dim3(64, 8), 256>>>(fl, sum + 704, sqs + 704, fg, fe,
                                            (float*)d_out, 1.f / (8.f * 16384.f));
}